// round 3
// baseline (speedup 1.0000x reference)
#include <cuda_runtime.h>
#include <math_constants.h>

#define NB  4
#define SEQ 2048
#define DM  1024
#define NH  16
#define HD  64

// Scratch (device globals: allocation inside kernel_launch is forbidden)
__device__ float g_Q[NB * NH * SEQ * HD];     // [b,h,s,m]
__device__ float g_K[NB * NH * SEQ * HD];     // [b,h,s,m]
__device__ float g_V[NB * NH * SEQ * HD];     // [b,h,s,m]
__device__ float g_ctx[NB * SEQ * NH * HD];   // [b,s,h,m]  (== [8192,1024] row-major)

// ---------------------------------------------------------------------------
// Fused QKV projection: C[8192,3072] = X[8192,1024] * [Wq|Wk|Wv]
// Tiles 128x128x16, 256 threads, 8x8 per thread. Writes scattered to
// g_Q/g_K/g_V in [b,h,s,m] layout for the attention kernel.
// grid = (24, 64)
// ---------------------------------------------------------------------------
__global__ __launch_bounds__(256) void qkv_gemm_kernel(
    const float* __restrict__ X,
    const float* __restrict__ Wq,
    const float* __restrict__ Wk,
    const float* __restrict__ Wv)
{
    __shared__ float As[16][128];   // As[k][row]  (A transposed for LDS.128)
    __shared__ float Bs[16][128];   // Bs[k][col]

    const int tid  = threadIdx.x;
    const int row0 = blockIdx.y * 128;
    const int col0 = blockIdx.x * 128;          // 0..3071
    const int which = col0 >> 10;               // 0=q 1=k 2=v (1024 % 128 == 0)
    const int colw0 = col0 & 1023;
    const float* __restrict__ W = (which == 0) ? Wq : (which == 1) ? Wk : Wv;

    const int tx = tid & 15, ty = tid >> 4;
    const int tr = ty * 8, tc = tx * 8;

    float acc[8][8];
#pragma unroll
    for (int i = 0; i < 8; i++)
#pragma unroll
        for (int j = 0; j < 8; j++) acc[i][j] = 0.f;

    for (int k0 = 0; k0 < DM; k0 += 16) {
        // A tile: 128 rows x 16 k (2 float4 per thread)
#pragma unroll
        for (int it = 0; it < 2; it++) {
            int id = tid * 2 + it;
            int r  = id >> 2;
            int kq = (id & 3) * 4;
            float4 a4 = *(const float4*)&X[(row0 + r) * DM + k0 + kq];
            As[kq + 0][r] = a4.x;
            As[kq + 1][r] = a4.y;
            As[kq + 2][r] = a4.z;
            As[kq + 3][r] = a4.w;
        }
        // B tile: W[h,d,m] -> flat h*(DM*HD) + d*HD + m
#pragma unroll
        for (int it = 0; it < 8; it++) {
            int id = it * 256 + tid;
            int kk = id >> 7;
            int c  = id & 127;
            int gc = colw0 + c;
            int h  = gc >> 6, m = gc & 63;
            Bs[kk][c] = W[h * (DM * HD) + (k0 + kk) * HD + m];
        }
        __syncthreads();
#pragma unroll
        for (int kk = 0; kk < 16; kk++) {
            float a[8], b[8];
            *(float4*)&a[0] = *(const float4*)&As[kk][tr];
            *(float4*)&a[4] = *(const float4*)&As[kk][tr + 4];
            *(float4*)&b[0] = *(const float4*)&Bs[kk][tc];
            *(float4*)&b[4] = *(const float4*)&Bs[kk][tc + 4];
#pragma unroll
            for (int i = 0; i < 8; i++)
#pragma unroll
                for (int j = 0; j < 8; j++)
                    acc[i][j] = fmaf(a[i], b[j], acc[i][j]);
        }
        __syncthreads();
    }

    float* dst = (which == 0) ? g_Q : (which == 1) ? g_K : g_V;
#pragma unroll
    for (int i = 0; i < 8; i++) {
        int grow = row0 + tr + i;
        int b = grow >> 11, s = grow & (SEQ - 1);
#pragma unroll
        for (int j = 0; j < 8; j++) {
            int gc = colw0 + tc + j;
            int h = gc >> 6, m = gc & 63;
            dst[(((b * NH + h) * SEQ) + s) * HD + m] = acc[i][j];
        }
    }
}

// ---------------------------------------------------------------------------
// Flash attention: one block per (b,h, 64-row q-tile). Online softmax over
// 64-row k-tiles. 256 threads, 4x4 micro-tile of the 64x64 S tile.
// P tile aliases the K smem buffer -> 48 KB static smem exactly.
// grid = (SEQ/64, NB*NH)
// ---------------------------------------------------------------------------
__global__ __launch_bounds__(256) void attn_kernel()
{
    __shared__ float Qt[HD][64];     // Qt[m][i]   (pre-scaled by 1/sqrt(64))
    __shared__ float KtPs[64][64];   // first Kt[m][j], then reused as Ps[j][i]
    __shared__ float Vs[64][HD];     // Vs[j][c]

    const int bh = blockIdx.y;
    const int b  = bh >> 4, h = bh & 15;
    const int qt = blockIdx.x;

    const float* __restrict__ Qg = g_Q + (bh * SEQ + qt * 64) * HD;
    const float* __restrict__ Kg = g_K + bh * SEQ * HD;
    const float* __restrict__ Vg = g_V + bh * SEQ * HD;

    const int tid = threadIdx.x;
    const int tx = tid & 15, ty = tid >> 4;
    const int tr = ty * 4, tc = tx * 4;

    const float scale = 0.125f;  // 1/sqrt(64)
#pragma unroll
    for (int it = 0; it < 4; it++) {
        int id = it * 256 + tid;
        int r  = id >> 4;
        int mq = (id & 15) * 4;
        float4 q4 = *(const float4*)&Qg[r * HD + mq];
        Qt[mq + 0][r] = q4.x * scale;
        Qt[mq + 1][r] = q4.y * scale;
        Qt[mq + 2][r] = q4.z * scale;
        Qt[mq + 3][r] = q4.w * scale;
    }

    float mi[4], li[4], acc[4][4];
#pragma unroll
    for (int i = 0; i < 4; i++) {
        mi[i] = -CUDART_INF_F;
        li[i] = 0.f;
#pragma unroll
        for (int j = 0; j < 4; j++) acc[i][j] = 0.f;
    }

    for (int kt = 0; kt < SEQ / 64; kt++) {
        __syncthreads();   // previous-iter smem reads (and Qt stores) complete
        const float* Kb = Kg + kt * 64 * HD;
        const float* Vb = Vg + kt * 64 * HD;
#pragma unroll
        for (int it = 0; it < 4; it++) {
            int id = it * 256 + tid;
            int r  = id >> 4;
            int mq = (id & 15) * 4;
            float4 k4 = *(const float4*)&Kb[r * HD + mq];
            KtPs[mq + 0][r] = k4.x;
            KtPs[mq + 1][r] = k4.y;
            KtPs[mq + 2][r] = k4.z;
            KtPs[mq + 3][r] = k4.w;
            float4 v4 = *(const float4*)&Vb[r * HD + mq];
            *(float4*)&Vs[r][mq] = v4;
        }
        __syncthreads();

        // S tile: s[i][j] = sum_m Q[i][m]*K[j][m] (Q pre-scaled)
        float sv[4][4];
#pragma unroll
        for (int i = 0; i < 4; i++)
#pragma unroll
            for (int j = 0; j < 4; j++) sv[i][j] = 0.f;
#pragma unroll
        for (int m = 0; m < HD; m++) {
            float4 q4 = *(const float4*)&Qt[m][tr];
            float4 k4 = *(const float4*)&KtPs[m][tc];
            float qa[4] = {q4.x, q4.y, q4.z, q4.w};
            float ka[4] = {k4.x, k4.y, k4.z, k4.w};
#pragma unroll
            for (int i = 0; i < 4; i++)
#pragma unroll
                for (int j = 0; j < 4; j++)
                    sv[i][j] = fmaf(qa[i], ka[j], sv[i][j]);
        }

        // Online softmax update (row = 16 consecutive lanes within a warp)
#pragma unroll
        for (int i = 0; i < 4; i++) {
            float rm = fmaxf(fmaxf(sv[i][0], sv[i][1]), fmaxf(sv[i][2], sv[i][3]));
            rm = fmaxf(rm, __shfl_xor_sync(0xffffffffu, rm, 1));
            rm = fmaxf(rm, __shfl_xor_sync(0xffffffffu, rm, 2));
            rm = fmaxf(rm, __shfl_xor_sync(0xffffffffu, rm, 4));
            rm = fmaxf(rm, __shfl_xor_sync(0xffffffffu, rm, 8));
            float nm   = fmaxf(mi[i], rm);
            float corr = __expf(mi[i] - nm);
            mi[i] = nm;
            float rs = 0.f;
#pragma unroll
            for (int j = 0; j < 4; j++) {
                sv[i][j] = __expf(sv[i][j] - nm);
                rs += sv[i][j];
            }
            rs += __shfl_xor_sync(0xffffffffu, rs, 1);
            rs += __shfl_xor_sync(0xffffffffu, rs, 2);
            rs += __shfl_xor_sync(0xffffffffu, rs, 4);
            rs += __shfl_xor_sync(0xffffffffu, rs, 8);
            li[i] = li[i] * corr + rs;
#pragma unroll
            for (int j = 0; j < 4; j++) acc[i][j] *= corr;
        }

        __syncthreads();   // all Kt reads finished before overwriting with P
#pragma unroll
        for (int i = 0; i < 4; i++)
#pragma unroll
            for (int j = 0; j < 4; j++)
                KtPs[tc + j][tr + i] = sv[i][j];   // Ps[j][i]
        __syncthreads();

        // acc[i][c] += sum_j P[i][j] * V[j][c]
#pragma unroll 16
        for (int j = 0; j < 64; j++) {
            float4 p4 = *(const float4*)&KtPs[j][tr];
            float4 v4 = *(const float4*)&Vs[j][tc];
            float pa[4] = {p4.x, p4.y, p4.z, p4.w};
            float va[4] = {v4.x, v4.y, v4.z, v4.w};
#pragma unroll
            for (int i = 0; i < 4; i++)
#pragma unroll
                for (int c = 0; c < 4; c++)
                    acc[i][c] = fmaf(pa[i], va[c], acc[i][c]);
        }
    }

    // ctx[b,s,h,m]
#pragma unroll
    for (int i = 0; i < 4; i++) {
        float inv = 1.f / li[i];
        int s = qt * 64 + tr + i;
#pragma unroll
        for (int j = 0; j < 4; j++)
            g_ctx[((b * SEQ + s) * NH + h) * HD + tc + j] = acc[i][j] * inv;
    }
}

// ---------------------------------------------------------------------------
// Output projection: out[8192,1024] = ctx[8192,1024] * Wo[1024,1024]
// (Wo[h,m,d] flat IS row-major [h*64+m][d]; ctx stored [b,s,h,m] matches.)
// grid = (8, 64)
// ---------------------------------------------------------------------------
__global__ __launch_bounds__(256) void out_gemm_kernel(
    const float* __restrict__ Wo, float* __restrict__ Out)
{
    __shared__ float As[16][128];
    __shared__ float Bs[16][128];

    const int tid  = threadIdx.x;
    const int row0 = blockIdx.y * 128;
    const int col0 = blockIdx.x * 128;

    const int tx = tid & 15, ty = tid >> 4;
    const int tr = ty * 8, tc = tx * 8;

    float acc[8][8];
#pragma unroll
    for (int i = 0; i < 8; i++)
#pragma unroll
        for (int j = 0; j < 8; j++) acc[i][j] = 0.f;

    for (int k0 = 0; k0 < DM; k0 += 16) {
#pragma unroll
        for (int it = 0; it < 2; it++) {
            int id = tid * 2 + it;
            int r  = id >> 2;
            int kq = (id & 3) * 4;
            float4 a4 = *(const float4*)&g_ctx[(row0 + r) * DM + k0 + kq];
            As[kq + 0][r] = a4.x;
            As[kq + 1][r] = a4.y;
            As[kq + 2][r] = a4.z;
            As[kq + 3][r] = a4.w;
        }
#pragma unroll
        for (int it = 0; it < 2; it++) {
            int id = tid * 2 + it;
            int kk = id >> 5;
            int cq = (id & 31) * 4;
            *(float4*)&Bs[kk][cq] = *(const float4*)&Wo[(k0 + kk) * DM + col0 + cq];
        }
        __syncthreads();
#pragma unroll
        for (int kk = 0; kk < 16; kk++) {
            float a[8], bb[8];
            *(float4*)&a[0]  = *(const float4*)&As[kk][tr];
            *(float4*)&a[4]  = *(const float4*)&As[kk][tr + 4];
            *(float4*)&bb[0] = *(const float4*)&Bs[kk][tc];
            *(float4*)&bb[4] = *(const float4*)&Bs[kk][tc + 4];
#pragma unroll
            for (int i = 0; i < 8; i++)
#pragma unroll
                for (int j = 0; j < 8; j++)
                    acc[i][j] = fmaf(a[i], bb[j], acc[i][j]);
        }
        __syncthreads();
    }

#pragma unroll
    for (int i = 0; i < 8; i++) {
        int grow = row0 + tr + i;
#pragma unroll
        for (int j = 0; j < 8; j++)
            Out[grow * DM + col0 + tc + j] = acc[i][j];
    }
}

// ---------------------------------------------------------------------------
extern "C" void kernel_launch(void* const* d_in, const int* in_sizes, int n_in,
                              void* d_out, int out_size)
{
    (void)in_sizes; (void)n_in; (void)out_size;
    const float* x  = (const float*)d_in[0];
    const float* Wq = (const float*)d_in[1];
    const float* Wk = (const float*)d_in[2];
    const float* Wv = (const float*)d_in[3];
    const float* Wo = (const float*)d_in[4];
    float* out = (float*)d_out;

    qkv_gemm_kernel<<<dim3(24, 64), 256>>>(x, Wq, Wk, Wv);
    attn_kernel<<<dim3(SEQ / 64, NB * NH), 256>>>();
    out_gemm_kernel<<<dim3(8, 64), 256>>>(Wo, out);
}

// round 5
// speedup vs baseline: 4.1524x; 4.1524x over previous
#include <cuda_runtime.h>

#define NB  4
#define SEQ 2048
#define DM  1024
#define NH  16
#define HD  64

#define LDA 36    // As pitch (floats): (36*m + k) % 32 = (4m+k)%32 -> conflict-free frags
#define LDB 136   // Bs pitch: (136*k + n) % 32 = (8k+n)%32 -> conflict-free frags
#define LDK 68    // Ks pitch: (68*j + m) % 32 = (4j+m)%32
#define LDV 72    // Vs pitch: (72*j + c) % 32 = (8j+c)%32

// Scratch (device globals: allocation inside kernel_launch is forbidden)
__device__ float g_Q[NB * NH * SEQ * HD];     // [b,h,s,m]
__device__ float g_K[NB * NH * SEQ * HD];     // [b,h,s,m]
__device__ float g_V[NB * NH * SEQ * HD];     // [b,h,s,m]
__device__ float g_ctx[NB * SEQ * NH * HD];   // [b,s,h,m] == [8192,1024] row-major

__device__ __forceinline__ unsigned f2tf(float f) {
    unsigned u; asm("cvt.rna.tf32.f32 %0, %1;" : "=r"(u) : "f"(f)); return u;
}

// D += A*B, m16n8k8 tf32. A row-major frag (a0..a3), B col-major frag (b0,b1).
__device__ __forceinline__ void mma8(float4& d, unsigned a0, unsigned a1,
                                     unsigned a2, unsigned a3,
                                     unsigned b0, unsigned b1) {
    asm volatile(
        "mma.sync.aligned.m16n8k8.row.col.f32.tf32.tf32.f32 "
        "{%0,%1,%2,%3}, {%4,%5,%6,%7}, {%8,%9}, {%0,%1,%2,%3};"
        : "+f"(d.x), "+f"(d.y), "+f"(d.z), "+f"(d.w)
        : "r"(a0), "r"(a1), "r"(a2), "r"(a3), "r"(b0), "r"(b1));
}

__device__ __forceinline__ float4 tf4(float4 v) {
    float4 r;
    r.x = __uint_as_float(f2tf(v.x));
    r.y = __uint_as_float(f2tf(v.y));
    r.z = __uint_as_float(f2tf(v.z));
    r.w = __uint_as_float(f2tf(v.w));
    return r;
}

// ---------------------------------------------------------------------------
// QKV projection, TF32 tensor cores. C[8192,3072] = X * [Wq|Wk|Wv].
// Block 128x128x(K=32 tiles), 8 warps, warp tile 64x32 (4x4 m16n8 tiles).
// grid = (24, 64)
// ---------------------------------------------------------------------------
__global__ __launch_bounds__(256, 2) void qkv_gemm_tc(
    const float* __restrict__ X,
    const float* __restrict__ Wq,
    const float* __restrict__ Wk,
    const float* __restrict__ Wv)
{
    __shared__ float As[128 * LDA];   // row-major [r][k]
    __shared__ float Bs[32 * LDB];    // [k][n]

    const int tid  = threadIdx.x;
    const int row0 = blockIdx.y * 128;
    const int col0 = blockIdx.x * 128;
    const int which = col0 >> 10;
    const int colw0 = col0 & 1023;
    const float* __restrict__ W = (which == 0) ? Wq : (which == 1) ? Wk : Wv;

    const int warp = tid >> 5, lane = tid & 31;
    const int g = lane >> 2, t = lane & 3;
    const int wm = (warp & 1) * 64, wn = (warp >> 1) * 32;

    float4 acc[4][4];
#pragma unroll
    for (int i = 0; i < 4; i++)
#pragma unroll
        for (int j = 0; j < 4; j++) acc[i][j] = make_float4(0.f, 0.f, 0.f, 0.f);

    for (int k0 = 0; k0 < DM; k0 += 32) {
#pragma unroll
        for (int it = 0; it < 4; it++) {        // A: 128r x 32k
            int id = it * 256 + tid;
            int r = id >> 3, kq = (id & 7) * 4;
            float4 a = *(const float4*)&X[(row0 + r) * DM + k0 + kq];
            *(float4*)&As[r * LDA + kq] = tf4(a);
        }
#pragma unroll
        for (int it = 0; it < 4; it++) {        // B: 32k x 128n (W[h,d,m])
            int id = it * 256 + tid;
            int kk = id >> 5, nq = (id & 31) * 4;
            int gc = colw0 + nq, hh = gc >> 6, m = gc & 63;
            float4 b = *(const float4*)&W[hh * (DM * HD) + (k0 + kk) * HD + m];
            *(float4*)&Bs[kk * LDB + nq] = tf4(b);
        }
        __syncthreads();
#pragma unroll
        for (int ks = 0; ks < 4; ks++) {
            const int kk = ks * 8;
            unsigned a[4][4], b[4][2];
#pragma unroll
            for (int mt = 0; mt < 4; mt++) {
                const float* p  = &As[(wm + mt * 16 + g) * LDA + kk + t];
                const float* p8 = p + 8 * LDA;
                a[mt][0] = __float_as_uint(p[0]);
                a[mt][2] = __float_as_uint(p[4]);
                a[mt][1] = __float_as_uint(p8[0]);
                a[mt][3] = __float_as_uint(p8[4]);
            }
#pragma unroll
            for (int nt = 0; nt < 4; nt++) {
                const float* p = &Bs[(kk + t) * LDB + wn + nt * 8 + g];
                b[nt][0] = __float_as_uint(p[0]);
                b[nt][1] = __float_as_uint(p[4 * LDB]);
            }
#pragma unroll
            for (int mt = 0; mt < 4; mt++)
#pragma unroll
                for (int nt = 0; nt < 4; nt++)
                    mma8(acc[mt][nt], a[mt][0], a[mt][1], a[mt][2], a[mt][3],
                         b[nt][0], b[nt][1]);
        }
        __syncthreads();
    }

    float* dst = (which == 0) ? g_Q : (which == 1) ? g_K : g_V;
#pragma unroll
    for (int mt = 0; mt < 4; mt++) {
        int r0 = row0 + wm + mt * 16 + g;
        int r1 = r0 + 8;
        int b0i = r0 >> 11, s0 = r0 & (SEQ - 1);
        int b1i = r1 >> 11, s1 = r1 & (SEQ - 1);
#pragma unroll
        for (int nt = 0; nt < 4; nt++) {
            int gc = colw0 + wn + nt * 8 + 2 * t;
            int hh = gc >> 6, m = gc & 63;
            *(float2*)&dst[(((b0i * NH + hh) * SEQ) + s0) * HD + m] =
                make_float2(acc[mt][nt].x, acc[mt][nt].y);
            *(float2*)&dst[(((b1i * NH + hh) * SEQ) + s1) * HD + m] =
                make_float2(acc[mt][nt].z, acc[mt][nt].w);
        }
    }
}

// ---------------------------------------------------------------------------
// Flash attention, TF32 tensor cores. Block: 8 warps, q-tile 128 rows
// (warp owns 16), k-tiles of 64. P stays in registers (shuffle relayout).
// grid = (SEQ/128, NB*NH)
// ---------------------------------------------------------------------------
__global__ __launch_bounds__(256, 2) void attn_tc()
{
    __shared__ float Ks[64 * LDK];   // [j][m]
    __shared__ float Vs[64 * LDV];   // [j][c]

    const int tid = threadIdx.x;
    const int warp = tid >> 5, lane = tid & 31;
    const int g = lane >> 2, t = lane & 3;
    const int bh = blockIdx.y;
    const int b = bh >> 4, h = bh & 15;
    const int qt = blockIdx.x;
    const int i0 = warp * 16;

    const float* __restrict__ Qg = g_Q + (bh * SEQ + qt * 128) * HD;
    const float* __restrict__ Kg = g_K + bh * SEQ * HD;
    const float* __restrict__ Vg = g_V + bh * SEQ * HD;

    // Q fragments, loaded once, pre-scaled by 1/sqrt(64)
    unsigned ql[8][4];
    {
        const float* qr0 = &Qg[(i0 + g) * HD];
        const float* qr1 = &Qg[(i0 + g + 8) * HD];
#pragma unroll
        for (int ks = 0; ks < 8; ks++) {
            ql[ks][0] = f2tf(qr0[ks * 8 + t]     * 0.125f);
            ql[ks][2] = f2tf(qr0[ks * 8 + t + 4] * 0.125f);
            ql[ks][1] = f2tf(qr1[ks * 8 + t]     * 0.125f);
            ql[ks][3] = f2tf(qr1[ks * 8 + t + 4] * 0.125f);
        }
    }

    float4 o[8];
#pragma unroll
    for (int nt = 0; nt < 8; nt++) o[nt] = make_float4(0.f, 0.f, 0.f, 0.f);
    float m0v = -1e30f, m1v = -1e30f, l0 = 0.f, l1 = 0.f;

    for (int kt = 0; kt < SEQ / 64; kt++) {
        __syncthreads();
        const float* Kb = Kg + kt * 64 * HD;
        const float* Vb = Vg + kt * 64 * HD;
#pragma unroll
        for (int it = 0; it < 4; it++) {
            int id = it * 256 + tid;
            int j = id >> 4, mq = (id & 15) * 4;
            *(float4*)&Ks[j * LDK + mq] = tf4(*(const float4*)&Kb[j * HD + mq]);
            *(float4*)&Vs[j * LDV + mq] = tf4(*(const float4*)&Vb[j * HD + mq]);
        }
        __syncthreads();

        // S = Q K^T  (warp: 16 x 64)
        float4 s[8];
#pragma unroll
        for (int nt = 0; nt < 8; nt++) s[nt] = make_float4(0.f, 0.f, 0.f, 0.f);
#pragma unroll
        for (int ks = 0; ks < 8; ks++) {
            const int kk = ks * 8;
#pragma unroll
            for (int nt = 0; nt < 8; nt++) {
                const float* p = &Ks[(nt * 8 + g) * LDK + kk + t];
                mma8(s[nt], ql[ks][0], ql[ks][1], ql[ks][2], ql[ks][3],
                     __float_as_uint(p[0]), __float_as_uint(p[4]));
            }
        }

        // Online softmax. Thread holds rows g (x,y) and g+8 (z,w).
        float rm0 = -1e30f, rm1 = -1e30f;
#pragma unroll
        for (int nt = 0; nt < 8; nt++) {
            rm0 = fmaxf(rm0, fmaxf(s[nt].x, s[nt].y));
            rm1 = fmaxf(rm1, fmaxf(s[nt].z, s[nt].w));
        }
        rm0 = fmaxf(rm0, __shfl_xor_sync(~0u, rm0, 1));
        rm0 = fmaxf(rm0, __shfl_xor_sync(~0u, rm0, 2));
        rm1 = fmaxf(rm1, __shfl_xor_sync(~0u, rm1, 1));
        rm1 = fmaxf(rm1, __shfl_xor_sync(~0u, rm1, 2));
        float nm0 = fmaxf(m0v, rm0), nm1 = fmaxf(m1v, rm1);
        float c0 = __expf(m0v - nm0), c1 = __expf(m1v - nm1);
        m0v = nm0; m1v = nm1;
        float rs0 = 0.f, rs1 = 0.f;
#pragma unroll
        for (int nt = 0; nt < 8; nt++) {
            s[nt].x = __expf(s[nt].x - nm0);
            s[nt].y = __expf(s[nt].y - nm0);
            s[nt].z = __expf(s[nt].z - nm1);
            s[nt].w = __expf(s[nt].w - nm1);
            rs0 += s[nt].x + s[nt].y;
            rs1 += s[nt].z + s[nt].w;
        }
        rs0 += __shfl_xor_sync(~0u, rs0, 1);
        rs0 += __shfl_xor_sync(~0u, rs0, 2);
        rs1 += __shfl_xor_sync(~0u, rs1, 1);
        rs1 += __shfl_xor_sync(~0u, rs1, 2);
        l0 = l0 * c0 + rs0;
        l1 = l1 * c1 + rs1;
#pragma unroll
        for (int nt = 0; nt < 8; nt++) {
            o[nt].x *= c0; o[nt].y *= c0;
            o[nt].z *= c1; o[nt].w *= c1;
        }

        // O += P V. P C-frag -> A-frag relayout via intra-group shuffles:
        // A col jt*8+t lives in source lane (lane&~3)+(t>>1), reg .x/.y (parity).
        const int s0l = (lane & ~3) | (t >> 1);
        const int s2l = s0l + 2;
        const bool odd = (t & 1) != 0;
#pragma unroll
        for (int jt = 0; jt < 8; jt++) {
            float vx0 = __shfl_sync(~0u, s[jt].x, s0l);
            float vy0 = __shfl_sync(~0u, s[jt].y, s0l);
            float vz0 = __shfl_sync(~0u, s[jt].z, s0l);
            float vw0 = __shfl_sync(~0u, s[jt].w, s0l);
            float vx2 = __shfl_sync(~0u, s[jt].x, s2l);
            float vy2 = __shfl_sync(~0u, s[jt].y, s2l);
            float vz2 = __shfl_sync(~0u, s[jt].z, s2l);
            float vw2 = __shfl_sync(~0u, s[jt].w, s2l);
            unsigned a0 = __float_as_uint(odd ? vy0 : vx0);
            unsigned a1 = __float_as_uint(odd ? vw0 : vz0);
            unsigned a2 = __float_as_uint(odd ? vy2 : vx2);
            unsigned a3 = __float_as_uint(odd ? vw2 : vz2);
#pragma unroll
            for (int nt = 0; nt < 8; nt++) {
                const float* p = &Vs[(jt * 8 + t) * LDV + nt * 8 + g];
                mma8(o[nt], a0, a1, a2, a3,
                     __float_as_uint(p[0]), __float_as_uint(p[4 * LDV]));
            }
        }
    }

    const float inv0 = 1.f / l0, inv1 = 1.f / l1;
    const int sr0 = qt * 128 + i0 + g;
    const int sr1 = sr0 + 8;
    float* base0 = &g_ctx[((b * SEQ + sr0) * NH + h) * HD];
    float* base1 = &g_ctx[((b * SEQ + sr1) * NH + h) * HD];
#pragma unroll
    for (int nt = 0; nt < 8; nt++) {
        int c = nt * 8 + 2 * t;
        *(float2*)&base0[c] = make_float2(o[nt].x * inv0, o[nt].y * inv0);
        *(float2*)&base1[c] = make_float2(o[nt].z * inv1, o[nt].w * inv1);
    }
}

// ---------------------------------------------------------------------------
// Output projection, TF32: out[8192,1024] = ctx * Wo[1024,1024].
// grid = (8, 64)
// ---------------------------------------------------------------------------
__global__ __launch_bounds__(256, 2) void out_gemm_tc(
    const float* __restrict__ Wo, float* __restrict__ Out)
{
    __shared__ float As[128 * LDA];
    __shared__ float Bs[32 * LDB];

    const int tid  = threadIdx.x;
    const int row0 = blockIdx.y * 128;
    const int col0 = blockIdx.x * 128;

    const int warp = tid >> 5, lane = tid & 31;
    const int g = lane >> 2, t = lane & 3;
    const int wm = (warp & 1) * 64, wn = (warp >> 1) * 32;

    float4 acc[4][4];
#pragma unroll
    for (int i = 0; i < 4; i++)
#pragma unroll
        for (int j = 0; j < 4; j++) acc[i][j] = make_float4(0.f, 0.f, 0.f, 0.f);

    for (int k0 = 0; k0 < DM; k0 += 32) {
#pragma unroll
        for (int it = 0; it < 4; it++) {
            int id = it * 256 + tid;
            int r = id >> 3, kq = (id & 7) * 4;
            float4 a = *(const float4*)&g_ctx[(row0 + r) * DM + k0 + kq];
            *(float4*)&As[r * LDA + kq] = tf4(a);
        }
#pragma unroll
        for (int it = 0; it < 4; it++) {
            int id = it * 256 + tid;
            int kk = id >> 5, nq = (id & 31) * 4;
            float4 b = *(const float4*)&Wo[(k0 + kk) * DM + col0 + nq];
            *(float4*)&Bs[kk * LDB + nq] = tf4(b);
        }
        __syncthreads();
#pragma unroll
        for (int ks = 0; ks < 4; ks++) {
            const int kk = ks * 8;
            unsigned a[4][4], b[4][2];
#pragma unroll
            for (int mt = 0; mt < 4; mt++) {
                const float* p  = &As[(wm + mt * 16 + g) * LDA + kk + t];
                const float* p8 = p + 8 * LDA;
                a[mt][0] = __float_as_uint(p[0]);
                a[mt][2] = __float_as_uint(p[4]);
                a[mt][1] = __float_as_uint(p8[0]);
                a[mt][3] = __float_as_uint(p8[4]);
            }
#pragma unroll
            for (int nt = 0; nt < 4; nt++) {
                const float* p = &Bs[(kk + t) * LDB + wn + nt * 8 + g];
                b[nt][0] = __float_as_uint(p[0]);
                b[nt][1] = __float_as_uint(p[4 * LDB]);
            }
#pragma unroll
            for (int mt = 0; mt < 4; mt++)
#pragma unroll
                for (int nt = 0; nt < 4; nt++)
                    mma8(acc[mt][nt], a[mt][0], a[mt][1], a[mt][2], a[mt][3],
                         b[nt][0], b[nt][1]);
        }
        __syncthreads();
    }

#pragma unroll
    for (int mt = 0; mt < 4; mt++) {
        int r0 = row0 + wm + mt * 16 + g;
        int r1 = r0 + 8;
#pragma unroll
        for (int nt = 0; nt < 4; nt++) {
            int gc = col0 + wn + nt * 8 + 2 * t;
            *(float2*)&Out[r0 * DM + gc] = make_float2(acc[mt][nt].x, acc[mt][nt].y);
            *(float2*)&Out[r1 * DM + gc] = make_float2(acc[mt][nt].z, acc[mt][nt].w);
        }
    }
}

// ---------------------------------------------------------------------------
extern "C" void kernel_launch(void* const* d_in, const int* in_sizes, int n_in,
                              void* d_out, int out_size)
{
    (void)in_sizes; (void)n_in; (void)out_size;
    const float* x  = (const float*)d_in[0];
    const float* Wq = (const float*)d_in[1];
    const float* Wk = (const float*)d_in[2];
    const float* Wv = (const float*)d_in[3];
    const float* Wo = (const float*)d_in[4];
    float* out = (float*)d_out;

    qkv_gemm_tc<<<dim3(24, 64), 256>>>(x, Wq, Wk, Wv);
    attn_tc<<<dim3(SEQ / 128, NB * NH), 256>>>();
    out_gemm_tc<<<dim3(8, 64), 256>>>(Wo, out);
}

// round 6
// speedup vs baseline: 4.3209x; 1.0406x over previous
#include <cuda_runtime.h>

#define NB  4
#define SEQ 2048
#define DM  1024
#define NH  16
#define HD  64

#define LDA 36    // As pitch: (36*m+k)%32 = (4m+k)%32 -> conflict-free frag loads
#define LDB 136   // Bs pitch: (136*k+n)%32 = (8k+n)%32
#define LDK 68    // Ks pitch
#define LDV 72    // Vs pitch

#define A_STG (128 * LDA)                      // floats per A stage
#define B_STG (32 * LDB)                       // floats per B stage
#define K_STG (64 * LDK)
#define V_STG (64 * LDV)
#define DYN_BYTES (2 * (A_STG + B_STG) * 4)    // 71680 B (== 2*(K_STG+V_STG)*4)

// Scratch (device globals: allocation inside kernel_launch is forbidden)
__device__ float g_Q[NB * NH * SEQ * HD];     // [b,h,s,m]
__device__ float g_K[NB * NH * SEQ * HD];     // [b,h,s,m]
__device__ float g_V[NB * NH * SEQ * HD];     // [b,h,s,m]
__device__ float g_ctx[NB * SEQ * NH * HD];   // [b,s,h,m] == [8192,1024] row-major

__device__ __forceinline__ unsigned f2tf(float f) {
    unsigned u; asm("cvt.rna.tf32.f32 %0, %1;" : "=r"(u) : "f"(f)); return u;
}

__device__ __forceinline__ void cpa16(float* dst, const float* src) {
    unsigned ds = (unsigned)__cvta_generic_to_shared(dst);
    asm volatile("cp.async.cg.shared.global [%0], [%1], 16;" :: "r"(ds), "l"(src));
}
__device__ __forceinline__ void cpa_commit() {
    asm volatile("cp.async.commit_group;" ::: "memory");
}
__device__ __forceinline__ void cpa_wait1() {
    asm volatile("cp.async.wait_group 1;" ::: "memory");
}
__device__ __forceinline__ void cpa_wait0() {
    asm volatile("cp.async.wait_group 0;" ::: "memory");
}

// D += A*B, m16n8k8 tf32. A row-major frag (a0..a3), B col-major frag (b0,b1).
__device__ __forceinline__ void mma8(float4& d, unsigned a0, unsigned a1,
                                     unsigned a2, unsigned a3,
                                     unsigned b0, unsigned b1) {
    asm volatile(
        "mma.sync.aligned.m16n8k8.row.col.f32.tf32.tf32.f32 "
        "{%0,%1,%2,%3}, {%4,%5,%6,%7}, {%8,%9}, {%0,%1,%2,%3};"
        : "+f"(d.x), "+f"(d.y), "+f"(d.z), "+f"(d.w)
        : "r"(a0), "r"(a1), "r"(a2), "r"(a3), "r"(b0), "r"(b1));
}

// ---------------------------------------------------------------------------
// QKV projection, TF32 + cp.async double buffer. grid = (24, 64)
// ---------------------------------------------------------------------------
__global__ __launch_bounds__(256, 2) void qkv_gemm_tc(
    const float* __restrict__ X,
    const float* __restrict__ Wq,
    const float* __restrict__ Wk,
    const float* __restrict__ Wv)
{
    extern __shared__ float sm[];
    float* Asm = sm;                 // 2 stages of 128 x LDA
    float* Bsm = sm + 2 * A_STG;     // 2 stages of 32 x LDB

    const int tid  = threadIdx.x;
    const int row0 = blockIdx.y * 128;
    const int col0 = blockIdx.x * 128;
    const int which = col0 >> 10;
    const int colw0 = col0 & 1023;
    const float* __restrict__ W = (which == 0) ? Wq : (which == 1) ? Wk : Wv;

    const int warp = tid >> 5, lane = tid & 31;
    const int g = lane >> 2, t = lane & 3;
    const int wm = (warp & 1) * 64, wn = (warp >> 1) * 32;

    auto stage = [&](int s, int p) {
        const int k0 = s * 32;
        float* Ap = Asm + p * A_STG;
        float* Bp = Bsm + p * B_STG;
#pragma unroll
        for (int it = 0; it < 4; it++) {
            int id = it * 256 + tid;
            int r = id >> 3, kq = (id & 7) * 4;
            cpa16(&Ap[r * LDA + kq], &X[(row0 + r) * DM + k0 + kq]);
        }
#pragma unroll
        for (int it = 0; it < 4; it++) {
            int id = it * 256 + tid;
            int kk = id >> 5, nq = (id & 31) * 4;
            int gc = colw0 + nq, hh = gc >> 6, m = gc & 63;
            cpa16(&Bp[kk * LDB + nq], &W[hh * (DM * HD) + (k0 + kk) * HD + m]);
        }
        cpa_commit();
    };

    float4 acc[4][4];
#pragma unroll
    for (int i = 0; i < 4; i++)
#pragma unroll
        for (int j = 0; j < 4; j++) acc[i][j] = make_float4(0.f, 0.f, 0.f, 0.f);

    stage(0, 0);
#pragma unroll 1
    for (int s = 0; s < DM / 32; s++) {
        if (s + 1 < DM / 32) { stage(s + 1, (s + 1) & 1); cpa_wait1(); }
        else                 { cpa_wait0(); }
        __syncthreads();
        const float* A = Asm + (s & 1) * A_STG;
        const float* B = Bsm + (s & 1) * B_STG;
#pragma unroll
        for (int ks = 0; ks < 4; ks++) {
            const int kk = ks * 8;
            unsigned a[4][4], b[4][2];
#pragma unroll
            for (int mt = 0; mt < 4; mt++) {
                const float* p  = &A[(wm + mt * 16 + g) * LDA + kk + t];
                const float* p8 = p + 8 * LDA;
                a[mt][0] = f2tf(p[0]);
                a[mt][2] = f2tf(p[4]);
                a[mt][1] = f2tf(p8[0]);
                a[mt][3] = f2tf(p8[4]);
            }
#pragma unroll
            for (int nt = 0; nt < 4; nt++) {
                const float* p = &B[(kk + t) * LDB + wn + nt * 8 + g];
                b[nt][0] = f2tf(p[0]);
                b[nt][1] = f2tf(p[4 * LDB]);
            }
#pragma unroll
            for (int mt = 0; mt < 4; mt++)
#pragma unroll
                for (int nt = 0; nt < 4; nt++)
                    mma8(acc[mt][nt], a[mt][0], a[mt][1], a[mt][2], a[mt][3],
                         b[nt][0], b[nt][1]);
        }
        __syncthreads();
    }

    float* dst = (which == 0) ? g_Q : (which == 1) ? g_K : g_V;
#pragma unroll
    for (int mt = 0; mt < 4; mt++) {
        int r0 = row0 + wm + mt * 16 + g;
        int r1 = r0 + 8;
        int b0i = r0 >> 11, s0 = r0 & (SEQ - 1);
        int b1i = r1 >> 11, s1 = r1 & (SEQ - 1);
#pragma unroll
        for (int nt = 0; nt < 4; nt++) {
            int gc = colw0 + wn + nt * 8 + 2 * t;
            int hh = gc >> 6, m = gc & 63;
            *(float2*)&dst[(((b0i * NH + hh) * SEQ) + s0) * HD + m] =
                make_float2(acc[mt][nt].x, acc[mt][nt].y);
            *(float2*)&dst[(((b1i * NH + hh) * SEQ) + s1) * HD + m] =
                make_float2(acc[mt][nt].z, acc[mt][nt].w);
        }
    }
}

// ---------------------------------------------------------------------------
// Flash attention, TF32 + cp.async double-buffered K/V. grid = (SEQ/128, 64)
// ---------------------------------------------------------------------------
__global__ __launch_bounds__(256, 2) void attn_tc()
{
    extern __shared__ float sm[];
    float* Ksm = sm;                 // 2 stages of 64 x LDK
    float* Vsm = sm + 2 * K_STG;     // 2 stages of 64 x LDV

    const int tid = threadIdx.x;
    const int warp = tid >> 5, lane = tid & 31;
    const int g = lane >> 2, t = lane & 3;
    const int bh = blockIdx.y;
    const int b = bh >> 4, h = bh & 15;
    const int qt = blockIdx.x;
    const int i0 = warp * 16;

    const float* __restrict__ Qg = g_Q + (bh * SEQ + qt * 128) * HD;
    const float* __restrict__ Kg = g_K + bh * SEQ * HD;
    const float* __restrict__ Vg = g_V + bh * SEQ * HD;

    auto stage = [&](int kt, int p) {
        const float* Kb = Kg + kt * 64 * HD;
        const float* Vb = Vg + kt * 64 * HD;
        float* Kp = Ksm + p * K_STG;
        float* Vp = Vsm + p * V_STG;
#pragma unroll
        for (int it = 0; it < 4; it++) {
            int id = it * 256 + tid;
            int j = id >> 4, mq = (id & 15) * 4;
            cpa16(&Kp[j * LDK + mq], &Kb[j * HD + mq]);
            cpa16(&Vp[j * LDV + mq], &Vb[j * HD + mq]);
        }
        cpa_commit();
    };

    stage(0, 0);

    // Q fragments, loaded once, pre-scaled by 1/sqrt(64)
    unsigned ql[8][4];
    {
        const float* qr0 = &Qg[(i0 + g) * HD];
        const float* qr1 = &Qg[(i0 + g + 8) * HD];
#pragma unroll
        for (int ks = 0; ks < 8; ks++) {
            ql[ks][0] = f2tf(qr0[ks * 8 + t]     * 0.125f);
            ql[ks][2] = f2tf(qr0[ks * 8 + t + 4] * 0.125f);
            ql[ks][1] = f2tf(qr1[ks * 8 + t]     * 0.125f);
            ql[ks][3] = f2tf(qr1[ks * 8 + t + 4] * 0.125f);
        }
    }

    float4 o[8];
#pragma unroll
    for (int nt = 0; nt < 8; nt++) o[nt] = make_float4(0.f, 0.f, 0.f, 0.f);
    float m0v = -1e30f, m1v = -1e30f, l0 = 0.f, l1 = 0.f;

#pragma unroll 1
    for (int kt = 0; kt < SEQ / 64; kt++) {
        if (kt + 1 < SEQ / 64) { stage(kt + 1, (kt + 1) & 1); cpa_wait1(); }
        else                   { cpa_wait0(); }
        __syncthreads();
        const float* Ks = Ksm + (kt & 1) * K_STG;
        const float* Vs = Vsm + (kt & 1) * V_STG;

        // S = Q K^T  (warp: 16 x 64)
        float4 s[8];
#pragma unroll
        for (int nt = 0; nt < 8; nt++) s[nt] = make_float4(0.f, 0.f, 0.f, 0.f);
#pragma unroll
        for (int ks = 0; ks < 8; ks++) {
            const int kk = ks * 8;
#pragma unroll
            for (int nt = 0; nt < 8; nt++) {
                const float* p = &Ks[(nt * 8 + g) * LDK + kk + t];
                mma8(s[nt], ql[ks][0], ql[ks][1], ql[ks][2], ql[ks][3],
                     f2tf(p[0]), f2tf(p[4]));
            }
        }

        // Online softmax. Thread holds rows g (x,y) and g+8 (z,w).
        float rm0 = -1e30f, rm1 = -1e30f;
#pragma unroll
        for (int nt = 0; nt < 8; nt++) {
            rm0 = fmaxf(rm0, fmaxf(s[nt].x, s[nt].y));
            rm1 = fmaxf(rm1, fmaxf(s[nt].z, s[nt].w));
        }
        rm0 = fmaxf(rm0, __shfl_xor_sync(~0u, rm0, 1));
        rm0 = fmaxf(rm0, __shfl_xor_sync(~0u, rm0, 2));
        rm1 = fmaxf(rm1, __shfl_xor_sync(~0u, rm1, 1));
        rm1 = fmaxf(rm1, __shfl_xor_sync(~0u, rm1, 2));
        float nm0 = fmaxf(m0v, rm0), nm1 = fmaxf(m1v, rm1);
        float c0 = __expf(m0v - nm0), c1 = __expf(m1v - nm1);
        m0v = nm0; m1v = nm1;
        float rs0 = 0.f, rs1 = 0.f;
#pragma unroll
        for (int nt = 0; nt < 8; nt++) {
            s[nt].x = __expf(s[nt].x - nm0);
            s[nt].y = __expf(s[nt].y - nm0);
            s[nt].z = __expf(s[nt].z - nm1);
            s[nt].w = __expf(s[nt].w - nm1);
            rs0 += s[nt].x + s[nt].y;
            rs1 += s[nt].z + s[nt].w;
        }
        rs0 += __shfl_xor_sync(~0u, rs0, 1);
        rs0 += __shfl_xor_sync(~0u, rs0, 2);
        rs1 += __shfl_xor_sync(~0u, rs1, 1);
        rs1 += __shfl_xor_sync(~0u, rs1, 2);
        l0 = l0 * c0 + rs0;
        l1 = l1 * c1 + rs1;
#pragma unroll
        for (int nt = 0; nt < 8; nt++) {
            o[nt].x *= c0; o[nt].y *= c0;
            o[nt].z *= c1; o[nt].w *= c1;
        }

        // O += P V. P C-frag -> A-frag relayout via intra-group shuffles.
        const int s0l = (lane & ~3) | (t >> 1);
        const int s2l = s0l + 2;
        const bool odd = (t & 1) != 0;
#pragma unroll
        for (int jt = 0; jt < 8; jt++) {
            float vx0 = __shfl_sync(~0u, s[jt].x, s0l);
            float vy0 = __shfl_sync(~0u, s[jt].y, s0l);
            float vz0 = __shfl_sync(~0u, s[jt].z, s0l);
            float vw0 = __shfl_sync(~0u, s[jt].w, s0l);
            float vx2 = __shfl_sync(~0u, s[jt].x, s2l);
            float vy2 = __shfl_sync(~0u, s[jt].y, s2l);
            float vz2 = __shfl_sync(~0u, s[jt].z, s2l);
            float vw2 = __shfl_sync(~0u, s[jt].w, s2l);
            unsigned a0 = __float_as_uint(odd ? vy0 : vx0);
            unsigned a1 = __float_as_uint(odd ? vw0 : vz0);
            unsigned a2 = __float_as_uint(odd ? vy2 : vx2);
            unsigned a3 = __float_as_uint(odd ? vw2 : vz2);
#pragma unroll
            for (int nt = 0; nt < 8; nt++) {
                const float* p = &Vs[(jt * 8 + t) * LDV + nt * 8 + g];
                mma8(o[nt], a0, a1, a2, a3, f2tf(p[0]), f2tf(p[4 * LDV]));
            }
        }
        __syncthreads();
    }

    const float inv0 = 1.f / l0, inv1 = 1.f / l1;
    const int sr0 = qt * 128 + i0 + g;
    const int sr1 = sr0 + 8;
    float* base0 = &g_ctx[((b * SEQ + sr0) * NH + h) * HD];
    float* base1 = &g_ctx[((b * SEQ + sr1) * NH + h) * HD];
#pragma unroll
    for (int nt = 0; nt < 8; nt++) {
        int c = nt * 8 + 2 * t;
        *(float2*)&base0[c] = make_float2(o[nt].x * inv0, o[nt].y * inv0);
        *(float2*)&base1[c] = make_float2(o[nt].z * inv1, o[nt].w * inv1);
    }
}

// ---------------------------------------------------------------------------
// Output projection, TF32 + cp.async double buffer. grid = (8, 64)
// ---------------------------------------------------------------------------
__global__ __launch_bounds__(256, 2) void out_gemm_tc(
    const float* __restrict__ Wo, float* __restrict__ Out)
{
    extern __shared__ float sm[];
    float* Asm = sm;
    float* Bsm = sm + 2 * A_STG;

    const int tid  = threadIdx.x;
    const int row0 = blockIdx.y * 128;
    const int col0 = blockIdx.x * 128;

    const int warp = tid >> 5, lane = tid & 31;
    const int g = lane >> 2, t = lane & 3;
    const int wm = (warp & 1) * 64, wn = (warp >> 1) * 32;

    auto stage = [&](int s, int p) {
        const int k0 = s * 32;
        float* Ap = Asm + p * A_STG;
        float* Bp = Bsm + p * B_STG;
#pragma unroll
        for (int it = 0; it < 4; it++) {
            int id = it * 256 + tid;
            int r = id >> 3, kq = (id & 7) * 4;
            cpa16(&Ap[r * LDA + kq], &g_ctx[(row0 + r) * DM + k0 + kq]);
        }
#pragma unroll
        for (int it = 0; it < 4; it++) {
            int id = it * 256 + tid;
            int kk = id >> 5, nq = (id & 31) * 4;
            cpa16(&Bp[kk * LDB + nq], &Wo[(k0 + kk) * DM + col0 + nq]);
        }
        cpa_commit();
    };

    float4 acc[4][4];
#pragma unroll
    for (int i = 0; i < 4; i++)
#pragma unroll
        for (int j = 0; j < 4; j++) acc[i][j] = make_float4(0.f, 0.f, 0.f, 0.f);

    stage(0, 0);
#pragma unroll 1
    for (int s = 0; s < DM / 32; s++) {
        if (s + 1 < DM / 32) { stage(s + 1, (s + 1) & 1); cpa_wait1(); }
        else                 { cpa_wait0(); }
        __syncthreads();
        const float* A = Asm + (s & 1) * A_STG;
        const float* B = Bsm + (s & 1) * B_STG;
#pragma unroll
        for (int ks = 0; ks < 4; ks++) {
            const int kk = ks * 8;
            unsigned a[4][4], b[4][2];
#pragma unroll
            for (int mt = 0; mt < 4; mt++) {
                const float* p  = &A[(wm + mt * 16 + g) * LDA + kk + t];
                const float* p8 = p + 8 * LDA;
                a[mt][0] = f2tf(p[0]);
                a[mt][2] = f2tf(p[4]);
                a[mt][1] = f2tf(p8[0]);
                a[mt][3] = f2tf(p8[4]);
            }
#pragma unroll
            for (int nt = 0; nt < 4; nt++) {
                const float* p = &B[(kk + t) * LDB + wn + nt * 8 + g];
                b[nt][0] = f2tf(p[0]);
                b[nt][1] = f2tf(p[4 * LDB]);
            }
#pragma unroll
            for (int mt = 0; mt < 4; mt++)
#pragma unroll
                for (int nt = 0; nt < 4; nt++)
                    mma8(acc[mt][nt], a[mt][0], a[mt][1], a[mt][2], a[mt][3],
                         b[nt][0], b[nt][1]);
        }
        __syncthreads();
    }

#pragma unroll
    for (int mt = 0; mt < 4; mt++) {
        int r0 = row0 + wm + mt * 16 + g;
        int r1 = r0 + 8;
#pragma unroll
        for (int nt = 0; nt < 4; nt++) {
            int gc = col0 + wn + nt * 8 + 2 * t;
            *(float2*)&Out[r0 * DM + gc] = make_float2(acc[mt][nt].x, acc[mt][nt].y);
            *(float2*)&Out[r1 * DM + gc] = make_float2(acc[mt][nt].z, acc[mt][nt].w);
        }
    }
}

// ---------------------------------------------------------------------------
extern "C" void kernel_launch(void* const* d_in, const int* in_sizes, int n_in,
                              void* d_out, int out_size)
{
    (void)in_sizes; (void)n_in; (void)out_size;
    const float* x  = (const float*)d_in[0];
    const float* Wq = (const float*)d_in[1];
    const float* Wk = (const float*)d_in[2];
    const float* Wv = (const float*)d_in[3];
    const float* Wo = (const float*)d_in[4];
    float* out = (float*)d_out;

    cudaFuncSetAttribute(qkv_gemm_tc, cudaFuncAttributeMaxDynamicSharedMemorySize, DYN_BYTES);
    cudaFuncSetAttribute(attn_tc,     cudaFuncAttributeMaxDynamicSharedMemorySize, DYN_BYTES);
    cudaFuncSetAttribute(out_gemm_tc, cudaFuncAttributeMaxDynamicSharedMemorySize, DYN_BYTES);

    qkv_gemm_tc<<<dim3(24, 64), 256, DYN_BYTES>>>(x, Wq, Wk, Wv);
    attn_tc<<<dim3(SEQ / 128, NB * NH), 256, DYN_BYTES>>>();
    out_gemm_tc<<<dim3(8, 64), 256, DYN_BYTES>>>(Wo, out);
}